// round 1
// baseline (speedup 1.0000x reference)
#include <cuda_runtime.h>

#define N_NODES 50000
#define D 128
#define DOUT 64
#define E_EDGES 800000

// Scratch (device globals — no allocation allowed)
__device__ __align__(16) float g_agg1[N_NODES * D];
__device__ __align__(16) float g_h1[N_NODES * D];
__device__ __align__(16) float g_agg2[N_NODES * D];
__device__ __align__(16) float g_cnt[N_NODES];
__device__ __align__(16) float g_Wc[D * D];
__device__ __align__(16) float g_bc[D];

// ---------------------------------------------------------------------------
// Prep: Wc = W_pre @ W1, bc = b_pre @ W1 + b1   (tiny, 2 MFLOP)
// ---------------------------------------------------------------------------
__global__ void prep_kernel(const float* __restrict__ W_pre,
                            const float* __restrict__ b_pre,
                            const float* __restrict__ W1,
                            const float* __restrict__ b1) {
    int c = threadIdx.x;
    int r = blockIdx.x;
    if (r < D) {
        float acc = 0.f;
#pragma unroll 8
        for (int k = 0; k < D; k++) acc += W_pre[r * D + k] * W1[k * D + c];
        g_Wc[r * D + c] = acc;
    } else {
        float acc = b1[c];
#pragma unroll 8
        for (int k = 0; k < D; k++) acc += b_pre[k] * W1[k * D + c];
        g_bc[c] = acc;
    }
}

// ---------------------------------------------------------------------------
// Init: agg1 = x (self-loop), cnt = 1
// ---------------------------------------------------------------------------
__global__ void init_kernel(const float* __restrict__ x) {
    int idx = blockIdx.x * blockDim.x + threadIdx.x;
    if (idx < N_NODES * D) g_agg1[idx] = x[idx];
    if (idx < N_NODES) g_cnt[idx] = 1.0f;
}

// ---------------------------------------------------------------------------
// Degrees: cnt[dst] += 1 per edge
// ---------------------------------------------------------------------------
__global__ void degree_kernel(const int* __restrict__ dst) {
    int e = blockIdx.x * blockDim.x + threadIdx.x;
    if (e < E_EDGES) atomicAdd(&g_cnt[dst[e]], 1.0f);
}

// ---------------------------------------------------------------------------
// Scatter-sum: warp per edge, float4 gather + red.global.add.v4.f32
// ---------------------------------------------------------------------------
__device__ __forceinline__ void red_add_v4(float* p, float4 v) {
    asm volatile("red.global.add.v4.f32 [%0], {%1, %2, %3, %4};"
                 :: "l"(p), "f"(v.x), "f"(v.y), "f"(v.z), "f"(v.w)
                 : "memory");
}

__global__ void scatter1_kernel(const float* __restrict__ x,
                                const int* __restrict__ src,
                                const int* __restrict__ dst) {
    int warp = (blockIdx.x * blockDim.x + threadIdx.x) >> 5;
    int lane = threadIdx.x & 31;
    if (warp >= E_EDGES) return;
    int s = __ldg(&src[warp]);
    int d = __ldg(&dst[warp]);
    float4 v = *reinterpret_cast<const float4*>(x + (size_t)s * D + lane * 4);
    red_add_v4(g_agg1 + (size_t)d * D + lane * 4, v);
}

__global__ void scatter2_kernel(const int* __restrict__ src,
                                const int* __restrict__ dst) {
    int warp = (blockIdx.x * blockDim.x + threadIdx.x) >> 5;
    int lane = threadIdx.x & 31;
    if (warp >= E_EDGES) return;
    int s = __ldg(&src[warp]);
    int d = __ldg(&dst[warp]);
    float4 v = *reinterpret_cast<const float4*>(g_h1 + (size_t)s * D + lane * 4);
    red_add_v4(g_agg2 + (size_t)d * D + lane * 4, v);
}

// ---------------------------------------------------------------------------
// GEMM1: h1 = relu((agg1/cnt) @ Wc + bc); also agg2 = h1 (self-loop seed)
// Block: 256 threads, 16 rows x 64 output cols (gridDim.y = 2 column tiles)
// ---------------------------------------------------------------------------
#define G1_ROWS 16
__global__ void gemm1_kernel() {
    __shared__ __align__(16) float wc_s[D * 64];        // 32 KB
    __shared__ __align__(16) float in_s[G1_ROWS][D];    // 8 KB
    int tid = threadIdx.x;
    int row0 = blockIdx.x * G1_ROWS;
    int cbase = blockIdx.y * 64;

    // load Wc column tile
#pragma unroll
    for (int i = tid; i < D * 64; i += 256) {
        int k = i >> 6, c = i & 63;
        wc_s[i] = g_Wc[k * D + cbase + c];
    }
    // load input rows, scaled by 1/cnt
#pragma unroll
    for (int i = tid; i < G1_ROWS * D; i += 256) {
        int r = i >> 7;
        int row = row0 + r;
        float v = 0.f;
        if (row < N_NODES) v = g_agg1[(size_t)row * D + (i & 127)] / g_cnt[row];
        in_s[r][i & 127] = v;
    }
    __syncthreads();

    int r = tid >> 4;
    int c4 = (tid & 15) * 4;
    float4 acc = make_float4(0.f, 0.f, 0.f, 0.f);
#pragma unroll 8
    for (int k = 0; k < D; k++) {
        float a = in_s[r][k];
        float4 w = *reinterpret_cast<const float4*>(&wc_s[k * 64 + c4]);
        acc.x += a * w.x; acc.y += a * w.y;
        acc.z += a * w.z; acc.w += a * w.w;
    }
    int row = row0 + r;
    if (row < N_NODES) {
        float4 b = *reinterpret_cast<const float4*>(&g_bc[cbase + c4]);
        float4 o;
        o.x = fmaxf(acc.x + b.x, 0.f);
        o.y = fmaxf(acc.y + b.y, 0.f);
        o.z = fmaxf(acc.z + b.z, 0.f);
        o.w = fmaxf(acc.w + b.w, 0.f);
        size_t off = (size_t)row * D + cbase + c4;
        *reinterpret_cast<float4*>(&g_h1[off]) = o;
        *reinterpret_cast<float4*>(&g_agg2[off]) = o;  // self-loop
    }
}

// ---------------------------------------------------------------------------
// GEMM2 + L2-normalize: out = normalize((agg2/cnt) @ W2 + b2)
// Block: 256 threads = 8 warps = 8 rows; lane handles 2 output cols
// ---------------------------------------------------------------------------
__global__ void gemm2_kernel(const float* __restrict__ W2,
                             const float* __restrict__ b2,
                             float* __restrict__ out) {
    __shared__ __align__(16) float w2_s[D * DOUT];   // 32 KB
    __shared__ __align__(16) float in_s[8][D];       // 4 KB
    int tid = threadIdx.x;
    int row0 = blockIdx.x * 8;

#pragma unroll
    for (int i = tid; i < D * DOUT; i += 256) w2_s[i] = W2[i];
#pragma unroll
    for (int i = tid; i < 8 * D; i += 256) {
        int r = i >> 7, row = row0 + r;
        float v = 0.f;
        if (row < N_NODES) v = g_agg2[(size_t)row * D + (i & 127)] / g_cnt[row];
        in_s[r][i & 127] = v;
    }
    __syncthreads();

    int warp = tid >> 5, lane = tid & 31;
    int row = row0 + warp;
    float a0 = 0.f, a1 = 0.f;
#pragma unroll 8
    for (int k = 0; k < D; k++) {
        float a = in_s[warp][k];
        float2 w = *reinterpret_cast<const float2*>(&w2_s[k * DOUT + lane * 2]);
        a0 += a * w.x; a1 += a * w.y;
    }
    float2 b = *reinterpret_cast<const float2*>(&b2[lane * 2]);
    a0 += b.x; a1 += b.y;
    float ss = a0 * a0 + a1 * a1;
#pragma unroll
    for (int o = 16; o; o >>= 1) ss += __shfl_xor_sync(0xffffffffu, ss, o);
    float inv = 1.0f / fmaxf(sqrtf(ss), 1e-12f);
    if (row < N_NODES) {
        float2 o2 = make_float2(a0 * inv, a1 * inv);
        *reinterpret_cast<float2*>(&out[(size_t)row * DOUT + lane * 2]) = o2;
    }
}

// ---------------------------------------------------------------------------
extern "C" void kernel_launch(void* const* d_in, const int* in_sizes, int n_in,
                              void* d_out, int out_size) {
    const float* x     = (const float*)d_in[0];
    const int*   ei    = (const int*)d_in[1];
    const float* W_pre = (const float*)d_in[2];
    const float* b_pre = (const float*)d_in[3];
    const float* W1    = (const float*)d_in[4];
    const float* b1    = (const float*)d_in[5];
    const float* W2    = (const float*)d_in[6];
    const float* b2    = (const float*)d_in[7];
    float* out = (float*)d_out;

    const int* src = ei;            // edge_index[0]
    const int* dst = ei + E_EDGES;  // edge_index[1]

    prep_kernel<<<D + 1, D>>>(W_pre, b_pre, W1, b1);
    init_kernel<<<(N_NODES * D + 255) / 256, 256>>>(x);
    degree_kernel<<<(E_EDGES + 255) / 256, 256>>>(dst);
    scatter1_kernel<<<(E_EDGES * 32 + 255) / 256, 256>>>(x, src, dst);
    dim3 g1((N_NODES + G1_ROWS - 1) / G1_ROWS, 2);
    gemm1_kernel<<<g1, 256>>>();
    scatter2_kernel<<<(E_EDGES * 32 + 255) / 256, 256>>>(src, dst);
    gemm2_kernel<<<(N_NODES + 7) / 8, 256>>>(W2, b2, out);
}

// round 2
// speedup vs baseline: 1.5251x; 1.5251x over previous
#include <cuda_runtime.h>

#define N_NODES 50000
#define D 128
#define DOUT 64
#define E_EDGES 800000

// Scratch (device globals — no allocation allowed)
__device__ __align__(16) float g_agg1[N_NODES * D];
__device__ __align__(16) float g_h1[N_NODES * D];
__device__ __align__(16) float g_h2[N_NODES * DOUT];
__device__ __align__(16) float g_agg2[N_NODES * DOUT];
__device__ float g_cnt[N_NODES];
__device__ float g_inv[N_NODES];
__device__ __align__(16) float g_Wc[D * D];
__device__ __align__(16) float g_bc[D];

// ---------------------------------------------------------------------------
// Prep: Wc = W_pre @ W1, bc = b_pre @ W1 + b1
// ---------------------------------------------------------------------------
__global__ void prep_kernel(const float* __restrict__ W_pre,
                            const float* __restrict__ b_pre,
                            const float* __restrict__ W1,
                            const float* __restrict__ b1) {
    int c = threadIdx.x;
    int r = blockIdx.x;
    if (r < D) {
        float acc = 0.f;
#pragma unroll 8
        for (int k = 0; k < D; k++) acc += W_pre[r * D + k] * W1[k * D + c];
        g_Wc[r * D + c] = acc;
    } else {
        float acc = b1[c];
#pragma unroll 8
        for (int k = 0; k < D; k++) acc += b_pre[k] * W1[k * D + c];
        g_bc[c] = acc;
    }
}

// ---------------------------------------------------------------------------
// Init: agg1 = x (self-loop), cnt = 1
// ---------------------------------------------------------------------------
__global__ void init_kernel(const float* __restrict__ x) {
    int idx = blockIdx.x * blockDim.x + threadIdx.x;
    if (idx < N_NODES * D) g_agg1[idx] = x[idx];
    if (idx < N_NODES) g_cnt[idx] = 1.0f;
}

__global__ void degree_kernel(const int* __restrict__ dst) {
    int e = blockIdx.x * blockDim.x + threadIdx.x;
    if (e < E_EDGES) atomicAdd(&g_cnt[dst[e]], 1.0f);
}

__global__ void inv_kernel() {
    int i = blockIdx.x * blockDim.x + threadIdx.x;
    if (i < N_NODES) g_inv[i] = 1.0f / g_cnt[i];
}

// ---------------------------------------------------------------------------
// Scatter-sum kernels: red.global.add.v4.f32
// ---------------------------------------------------------------------------
__device__ __forceinline__ void red_add_v4(float* p, float4 v) {
    asm volatile("red.global.add.v4.f32 [%0], {%1, %2, %3, %4};"
                 :: "l"(p), "f"(v.x), "f"(v.y), "f"(v.z), "f"(v.w)
                 : "memory");
}

// layer-1: 128-dim, warp per edge
__global__ void scatter1_kernel(const float* __restrict__ x,
                                const int* __restrict__ src,
                                const int* __restrict__ dst) {
    int warp = (blockIdx.x * blockDim.x + threadIdx.x) >> 5;
    int lane = threadIdx.x & 31;
    if (warp >= E_EDGES) return;
    int s = __ldg(&src[warp]);
    int d = __ldg(&dst[warp]);
    float4 v = *reinterpret_cast<const float4*>(x + (size_t)s * D + lane * 4);
    red_add_v4(g_agg1 + (size_t)d * D + lane * 4, v);
}

// layer-2: 64-dim, half-warp per edge (2 edges / warp)
__global__ void scatter2_kernel(const int* __restrict__ src,
                                const int* __restrict__ dst) {
    int gw = (blockIdx.x * blockDim.x + threadIdx.x) >> 5;
    int lane = threadIdx.x & 31;
    int e = gw * 2 + (lane >> 4);
    if (e >= E_EDGES) return;
    int l = lane & 15;
    int s = __ldg(&src[e]);
    int d = __ldg(&dst[e]);
    float4 v = *reinterpret_cast<const float4*>(g_h2 + (size_t)s * DOUT + l * 4);
    red_add_v4(g_agg2 + (size_t)d * DOUT + l * 4, v);
}

// ---------------------------------------------------------------------------
// GEMM1: h1 = relu((agg1 * inv) @ Wc + bc)
// 128x128 block tile, 256 threads, 8x8 register tile per thread
// dyn smem: Wc 64KB + in 128x129 ~64.5KB
// ---------------------------------------------------------------------------
#define ISTR (D + 1)
__global__ void gemm1_kernel() {
    extern __shared__ float sm[];
    float* wc = sm;              // D*D
    float* in = sm + D * D;      // 128 * ISTR
    int tid = threadIdx.x;
    int row0 = blockIdx.x * 128;

#pragma unroll
    for (int i = tid; i < D * D; i += 256) wc[i] = g_Wc[i];
#pragma unroll
    for (int i = tid; i < 128 * D; i += 256) {
        int r = i >> 7, k = i & 127;
        int row = row0 + r;
        float v = 0.f;
        if (row < N_NODES) v = g_agg1[(size_t)row * D + k] * g_inv[row];
        in[r * ISTR + k] = v;
    }
    __syncthreads();

    int ty = tid >> 4, tx = tid & 15;   // 16x16 threads
    float acc[8][8];
#pragma unroll
    for (int i = 0; i < 8; i++)
#pragma unroll
        for (int j = 0; j < 8; j++) acc[i][j] = 0.f;

#pragma unroll 4
    for (int k = 0; k < D; k++) {
        float a[8];
#pragma unroll
        for (int i = 0; i < 8; i++) a[i] = in[(ty * 8 + i) * ISTR + k];
        float4 w0 = *reinterpret_cast<const float4*>(&wc[k * D + tx * 8]);
        float4 w1 = *reinterpret_cast<const float4*>(&wc[k * D + tx * 8 + 4]);
        float w[8] = {w0.x, w0.y, w0.z, w0.w, w1.x, w1.y, w1.z, w1.w};
#pragma unroll
        for (int i = 0; i < 8; i++)
#pragma unroll
            for (int j = 0; j < 8; j++) acc[i][j] += a[i] * w[j];
    }

    int c = tx * 8;
    float4 b0 = *reinterpret_cast<const float4*>(&g_bc[c]);
    float4 b1 = *reinterpret_cast<const float4*>(&g_bc[c + 4]);
#pragma unroll
    for (int i = 0; i < 8; i++) {
        int row = row0 + ty * 8 + i;
        if (row < N_NODES) {
            float4 o0, o1;
            o0.x = fmaxf(acc[i][0] + b0.x, 0.f);
            o0.y = fmaxf(acc[i][1] + b0.y, 0.f);
            o0.z = fmaxf(acc[i][2] + b0.z, 0.f);
            o0.w = fmaxf(acc[i][3] + b0.w, 0.f);
            o1.x = fmaxf(acc[i][4] + b1.x, 0.f);
            o1.y = fmaxf(acc[i][5] + b1.y, 0.f);
            o1.z = fmaxf(acc[i][6] + b1.z, 0.f);
            o1.w = fmaxf(acc[i][7] + b1.w, 0.f);
            *reinterpret_cast<float4*>(&g_h1[(size_t)row * D + c]) = o0;
            *reinterpret_cast<float4*>(&g_h1[(size_t)row * D + c + 4]) = o1;
        }
    }
}

// ---------------------------------------------------------------------------
// GEMM2: h2 = h1 @ W2 (no bias here); also agg2 = h2 (self-loop seed)
// 128x64 block tile, 256 threads, 8x4 register tile per thread
// ---------------------------------------------------------------------------
__global__ void gemm2_kernel(const float* __restrict__ W2) {
    extern __shared__ float sm[];
    float* w2 = sm;                 // D*DOUT
    float* in = sm + D * DOUT;      // 128 * ISTR
    int tid = threadIdx.x;
    int row0 = blockIdx.x * 128;

#pragma unroll
    for (int i = tid; i < D * DOUT; i += 256) w2[i] = W2[i];
#pragma unroll
    for (int i = tid; i < 128 * D; i += 256) {
        int r = i >> 7, k = i & 127;
        int row = row0 + r;
        float v = 0.f;
        if (row < N_NODES) v = g_h1[(size_t)row * D + k];
        in[r * ISTR + k] = v;
    }
    __syncthreads();

    int ty = tid >> 4, tx = tid & 15;
    float acc[8][4];
#pragma unroll
    for (int i = 0; i < 8; i++)
#pragma unroll
        for (int j = 0; j < 4; j++) acc[i][j] = 0.f;

#pragma unroll 4
    for (int k = 0; k < D; k++) {
        float a[8];
#pragma unroll
        for (int i = 0; i < 8; i++) a[i] = in[(ty * 8 + i) * ISTR + k];
        float4 w = *reinterpret_cast<const float4*>(&w2[k * DOUT + tx * 4]);
#pragma unroll
        for (int i = 0; i < 8; i++) {
            acc[i][0] += a[i] * w.x;
            acc[i][1] += a[i] * w.y;
            acc[i][2] += a[i] * w.z;
            acc[i][3] += a[i] * w.w;
        }
    }

    int c = tx * 4;
#pragma unroll
    for (int i = 0; i < 8; i++) {
        int row = row0 + ty * 8 + i;
        if (row < N_NODES) {
            float4 o = make_float4(acc[i][0], acc[i][1], acc[i][2], acc[i][3]);
            size_t off = (size_t)row * DOUT + c;
            *reinterpret_cast<float4*>(&g_h2[off]) = o;
            *reinterpret_cast<float4*>(&g_agg2[off]) = o;  // self-loop seed
        }
    }
}

// ---------------------------------------------------------------------------
// Finalize: out = normalize(agg2 * inv + b2), warp per row
// ---------------------------------------------------------------------------
__global__ void final_kernel(const float* __restrict__ b2,
                             float* __restrict__ out) {
    int warp = (blockIdx.x * blockDim.x + threadIdx.x) >> 5;
    int lane = threadIdx.x & 31;
    if (warp >= N_NODES) return;
    float inv = g_inv[warp];
    float2 v = *reinterpret_cast<const float2*>(g_agg2 + (size_t)warp * DOUT + lane * 2);
    float2 b = *reinterpret_cast<const float2*>(b2 + lane * 2);
    float a0 = v.x * inv + b.x;
    float a1 = v.y * inv + b.y;
    float ss = a0 * a0 + a1 * a1;
#pragma unroll
    for (int o = 16; o; o >>= 1) ss += __shfl_xor_sync(0xffffffffu, ss, o);
    float s = 1.0f / fmaxf(sqrtf(ss), 1e-12f);
    float2 o2 = make_float2(a0 * s, a1 * s);
    *reinterpret_cast<float2*>(&out[(size_t)warp * DOUT + lane * 2]) = o2;
}

// ---------------------------------------------------------------------------
extern "C" void kernel_launch(void* const* d_in, const int* in_sizes, int n_in,
                              void* d_out, int out_size) {
    const float* x     = (const float*)d_in[0];
    const int*   ei    = (const int*)d_in[1];
    const float* W_pre = (const float*)d_in[2];
    const float* b_pre = (const float*)d_in[3];
    const float* W1    = (const float*)d_in[4];
    const float* b1    = (const float*)d_in[5];
    const float* W2    = (const float*)d_in[6];
    const float* b2    = (const float*)d_in[7];
    float* out = (float*)d_out;

    const int* src = ei;
    const int* dst = ei + E_EDGES;

    const int SMEM1 = (D * D + 128 * ISTR) * 4;      // ~128.5 KB
    const int SMEM2 = (D * DOUT + 128 * ISTR) * 4;   // ~96.5 KB
    static bool attr_set = false;
    if (!attr_set) {
        cudaFuncSetAttribute(gemm1_kernel, cudaFuncAttributeMaxDynamicSharedMemorySize, SMEM1);
        cudaFuncSetAttribute(gemm2_kernel, cudaFuncAttributeMaxDynamicSharedMemorySize, SMEM2);
        attr_set = true;
    }

    prep_kernel<<<D + 1, D>>>(W_pre, b_pre, W1, b1);
    init_kernel<<<(N_NODES * D + 255) / 256, 256>>>(x);
    degree_kernel<<<(E_EDGES + 255) / 256, 256>>>(dst);
    inv_kernel<<<(N_NODES + 255) / 256, 256>>>();
    scatter1_kernel<<<(E_EDGES * 32 + 255) / 256, 256>>>(x, src, dst);
    gemm1_kernel<<<(N_NODES + 127) / 128, 256, SMEM1>>>();
    gemm2_kernel<<<(N_NODES + 127) / 128, 256, SMEM2>>>(W2);
    scatter2_kernel<<<((E_EDGES / 2) * 32 + 255) / 256, 256>>>(src, dst);
    final_kernel<<<(N_NODES * 32 + 255) / 256, 256>>>(b2, out);
}

// round 3
// speedup vs baseline: 1.5866x; 1.0403x over previous
#include <cuda_runtime.h>

#define N_NODES 50000
#define D 128
#define DOUT 64
#define E_EDGES 800000

// Scratch (device globals — no allocation allowed)
__device__ __align__(16) float g_agg1[N_NODES * D];
__device__ __align__(16) float g_h1[N_NODES * D];
__device__ __align__(16) float g_h2[N_NODES * DOUT];
__device__ __align__(16) float g_Wc[D * D];
__device__ __align__(16) float g_bc[D];
__device__ int g_rowcnt[N_NODES];
__device__ int g_rowptr[N_NODES + 1];
__device__ int g_cursor[N_NODES];
__device__ int g_csr_src[E_EDGES];

// ---------------------------------------------------------------------------
// Prep: Wc = W_pre @ W1, bc = b_pre @ W1 + b1
// ---------------------------------------------------------------------------
__global__ void prep_kernel(const float* __restrict__ W_pre,
                            const float* __restrict__ b_pre,
                            const float* __restrict__ W1,
                            const float* __restrict__ b1) {
    int c = threadIdx.x;
    int r = blockIdx.x;
    if (r < D) {
        float acc = 0.f;
#pragma unroll 8
        for (int k = 0; k < D; k++) acc += W_pre[r * D + k] * W1[k * D + c];
        g_Wc[r * D + c] = acc;
    } else {
        float acc = b1[c];
#pragma unroll 8
        for (int k = 0; k < D; k++) acc += b_pre[k] * W1[k * D + c];
        g_bc[c] = acc;
    }
}

// ---------------------------------------------------------------------------
// CSR build: histogram -> scan -> fill
// ---------------------------------------------------------------------------
__global__ void zero_hist_kernel() {
    int i = blockIdx.x * blockDim.x + threadIdx.x;
    if (i < N_NODES) g_rowcnt[i] = 0;
}

__global__ void hist_kernel(const int* __restrict__ dst) {
    int e = blockIdx.x * blockDim.x + threadIdx.x;
    if (e < E_EDGES) atomicAdd(&g_rowcnt[dst[e]], 1);
}

__global__ void scan_kernel() {
    __shared__ int partial[1024];
    int t = threadIdx.x;
    const int CH = (N_NODES + 1023) / 1024;  // 49
    int beg = t * CH;
    int end = beg + CH; if (end > N_NODES) end = N_NODES;
    int s = 0;
    for (int i = beg; i < end; i++) s += g_rowcnt[i];
    partial[t] = s;
    __syncthreads();
    // Hillis-Steele inclusive scan
    for (int off = 1; off < 1024; off <<= 1) {
        int tmp = (t >= off) ? partial[t - off] : 0;
        __syncthreads();
        partial[t] += tmp;
        __syncthreads();
    }
    int run = partial[t] - s;  // exclusive prefix
    for (int i = beg; i < end; i++) {
        g_rowptr[i] = run;
        g_cursor[i] = run;
        run += g_rowcnt[i];
    }
    if (t == 1023) g_rowptr[N_NODES] = run;
}

__global__ void fill_kernel(const int* __restrict__ src,
                            const int* __restrict__ dst) {
    int e = blockIdx.x * blockDim.x + threadIdx.x;
    if (e < E_EDGES) {
        int pos = atomicAdd(&g_cursor[dst[e]], 1);
        g_csr_src[pos] = src[e];
    }
}

// ---------------------------------------------------------------------------
// Gather layer 1: agg1[i] = mean over {i} u in-neighbors of x  (128 dims)
// Warp per node; lane owns float4 at lane*4. No atomics.
// ---------------------------------------------------------------------------
__global__ void gather1_kernel(const float* __restrict__ x) {
    int node = (blockIdx.x * blockDim.x + threadIdx.x) >> 5;
    int lane = threadIdx.x & 31;
    if (node >= N_NODES) return;
    int beg = g_rowptr[node];
    int end = g_rowptr[node + 1];

    // self-loop
    float4 acc = *reinterpret_cast<const float4*>(x + (size_t)node * D + lane * 4);

    for (int base = beg; base < end; base += 32) {
        int idx = 0;
        if (base + lane < end) idx = __ldg(&g_csr_src[base + lane]);
        int m = end - base; if (m > 32) m = 32;
        for (int j = 0; j < m; j++) {
            int s = __shfl_sync(0xffffffffu, idx, j);
            float4 v = *reinterpret_cast<const float4*>(x + (size_t)s * D + lane * 4);
            acc.x += v.x; acc.y += v.y; acc.z += v.z; acc.w += v.w;
        }
    }
    float inv = 1.0f / (float)(end - beg + 1);
    acc.x *= inv; acc.y *= inv; acc.z *= inv; acc.w *= inv;
    *reinterpret_cast<float4*>(g_agg1 + (size_t)node * D + lane * 4) = acc;
}

// ---------------------------------------------------------------------------
// GEMM1: h1 = relu(agg1 @ Wc + bc)
// 128x128 block tile, 256 threads, 8x8 register tile
// ---------------------------------------------------------------------------
#define ISTR (D + 1)
__global__ void gemm1_kernel() {
    extern __shared__ float sm[];
    float* wc = sm;              // D*D
    float* in = sm + D * D;      // 128 * ISTR
    int tid = threadIdx.x;
    int row0 = blockIdx.x * 128;

#pragma unroll
    for (int i = tid; i < D * D; i += 256) wc[i] = g_Wc[i];
#pragma unroll
    for (int i = tid; i < 128 * D; i += 256) {
        int r = i >> 7, k = i & 127;
        int row = row0 + r;
        in[r * ISTR + k] = (row < N_NODES) ? g_agg1[(size_t)row * D + k] : 0.f;
    }
    __syncthreads();

    int ty = tid >> 4, tx = tid & 15;
    float acc[8][8];
#pragma unroll
    for (int i = 0; i < 8; i++)
#pragma unroll
        for (int j = 0; j < 8; j++) acc[i][j] = 0.f;

#pragma unroll 4
    for (int k = 0; k < D; k++) {
        float a[8];
#pragma unroll
        for (int i = 0; i < 8; i++) a[i] = in[(ty * 8 + i) * ISTR + k];
        float4 w0 = *reinterpret_cast<const float4*>(&wc[k * D + tx * 8]);
        float4 w1 = *reinterpret_cast<const float4*>(&wc[k * D + tx * 8 + 4]);
        float w[8] = {w0.x, w0.y, w0.z, w0.w, w1.x, w1.y, w1.z, w1.w};
#pragma unroll
        for (int i = 0; i < 8; i++)
#pragma unroll
            for (int j = 0; j < 8; j++) acc[i][j] += a[i] * w[j];
    }

    int c = tx * 8;
    float4 b0 = *reinterpret_cast<const float4*>(&g_bc[c]);
    float4 b1 = *reinterpret_cast<const float4*>(&g_bc[c + 4]);
#pragma unroll
    for (int i = 0; i < 8; i++) {
        int row = row0 + ty * 8 + i;
        if (row < N_NODES) {
            float4 o0, o1;
            o0.x = fmaxf(acc[i][0] + b0.x, 0.f);
            o0.y = fmaxf(acc[i][1] + b0.y, 0.f);
            o0.z = fmaxf(acc[i][2] + b0.z, 0.f);
            o0.w = fmaxf(acc[i][3] + b0.w, 0.f);
            o1.x = fmaxf(acc[i][4] + b1.x, 0.f);
            o1.y = fmaxf(acc[i][5] + b1.y, 0.f);
            o1.z = fmaxf(acc[i][6] + b1.z, 0.f);
            o1.w = fmaxf(acc[i][7] + b1.w, 0.f);
            *reinterpret_cast<float4*>(&g_h1[(size_t)row * D + c]) = o0;
            *reinterpret_cast<float4*>(&g_h1[(size_t)row * D + c + 4]) = o1;
        }
    }
}

// ---------------------------------------------------------------------------
// GEMM2: h2 = h1 @ W2 (bias deferred to epilogue of gather2)
// ---------------------------------------------------------------------------
__global__ void gemm2_kernel(const float* __restrict__ W2) {
    extern __shared__ float sm[];
    float* w2 = sm;                 // D*DOUT
    float* in = sm + D * DOUT;      // 128 * ISTR
    int tid = threadIdx.x;
    int row0 = blockIdx.x * 128;

#pragma unroll
    for (int i = tid; i < D * DOUT; i += 256) w2[i] = W2[i];
#pragma unroll
    for (int i = tid; i < 128 * D; i += 256) {
        int r = i >> 7, k = i & 127;
        int row = row0 + r;
        in[r * ISTR + k] = (row < N_NODES) ? g_h1[(size_t)row * D + k] : 0.f;
    }
    __syncthreads();

    int ty = tid >> 4, tx = tid & 15;
    float acc[8][4];
#pragma unroll
    for (int i = 0; i < 8; i++)
#pragma unroll
        for (int j = 0; j < 4; j++) acc[i][j] = 0.f;

#pragma unroll 4
    for (int k = 0; k < D; k++) {
        float a[8];
#pragma unroll
        for (int i = 0; i < 8; i++) a[i] = in[(ty * 8 + i) * ISTR + k];
        float4 w = *reinterpret_cast<const float4*>(&w2[k * DOUT + tx * 4]);
#pragma unroll
        for (int i = 0; i < 8; i++) {
            acc[i][0] += a[i] * w.x;
            acc[i][1] += a[i] * w.y;
            acc[i][2] += a[i] * w.z;
            acc[i][3] += a[i] * w.w;
        }
    }

    int c = tx * 4;
#pragma unroll
    for (int i = 0; i < 8; i++) {
        int row = row0 + ty * 8 + i;
        if (row < N_NODES) {
            float4 o = make_float4(acc[i][0], acc[i][1], acc[i][2], acc[i][3]);
            *reinterpret_cast<float4*>(&g_h2[(size_t)row * DOUT + c]) = o;
        }
    }
}

// ---------------------------------------------------------------------------
// Gather layer 2 + bias + L2 normalize, fused.  (64 dims)
// Warp per node; lane owns float2 at lane*2.
// ---------------------------------------------------------------------------
__global__ void gather2_kernel(const float* __restrict__ b2,
                               float* __restrict__ out) {
    int node = (blockIdx.x * blockDim.x + threadIdx.x) >> 5;
    int lane = threadIdx.x & 31;
    if (node >= N_NODES) return;
    int beg = g_rowptr[node];
    int end = g_rowptr[node + 1];

    // self-loop
    float2 acc = *reinterpret_cast<const float2*>(g_h2 + (size_t)node * DOUT + lane * 2);

    for (int base = beg; base < end; base += 32) {
        int idx = 0;
        if (base + lane < end) idx = __ldg(&g_csr_src[base + lane]);
        int m = end - base; if (m > 32) m = 32;
        for (int j = 0; j < m; j++) {
            int s = __shfl_sync(0xffffffffu, idx, j);
            float2 v = *reinterpret_cast<const float2*>(g_h2 + (size_t)s * DOUT + lane * 2);
            acc.x += v.x; acc.y += v.y;
        }
    }
    float inv = 1.0f / (float)(end - beg + 1);
    float2 b = *reinterpret_cast<const float2*>(b2 + lane * 2);
    float a0 = acc.x * inv + b.x;
    float a1 = acc.y * inv + b.y;
    float ss = a0 * a0 + a1 * a1;
#pragma unroll
    for (int o = 16; o; o >>= 1) ss += __shfl_xor_sync(0xffffffffu, ss, o);
    float s = 1.0f / fmaxf(sqrtf(ss), 1e-12f);
    float2 o2 = make_float2(a0 * s, a1 * s);
    *reinterpret_cast<float2*>(&out[(size_t)node * DOUT + lane * 2]) = o2;
}

// ---------------------------------------------------------------------------
extern "C" void kernel_launch(void* const* d_in, const int* in_sizes, int n_in,
                              void* d_out, int out_size) {
    const float* x     = (const float*)d_in[0];
    const int*   ei    = (const int*)d_in[1];
    const float* W_pre = (const float*)d_in[2];
    const float* b_pre = (const float*)d_in[3];
    const float* W1    = (const float*)d_in[4];
    const float* b1    = (const float*)d_in[5];
    const float* W2    = (const float*)d_in[6];
    const float* b2    = (const float*)d_in[7];
    float* out = (float*)d_out;

    const int* src = ei;
    const int* dst = ei + E_EDGES;

    const int SMEM1 = (D * D + 128 * ISTR) * 4;
    const int SMEM2 = (D * DOUT + 128 * ISTR) * 4;
    static bool attr_set = false;
    if (!attr_set) {
        cudaFuncSetAttribute(gemm1_kernel, cudaFuncAttributeMaxDynamicSharedMemorySize, SMEM1);
        cudaFuncSetAttribute(gemm2_kernel, cudaFuncAttributeMaxDynamicSharedMemorySize, SMEM2);
        attr_set = true;
    }

    prep_kernel<<<D + 1, D>>>(W_pre, b_pre, W1, b1);
    zero_hist_kernel<<<(N_NODES + 255) / 256, 256>>>();
    hist_kernel<<<(E_EDGES + 255) / 256, 256>>>(dst);
    scan_kernel<<<1, 1024>>>();
    fill_kernel<<<(E_EDGES + 255) / 256, 256>>>(src, dst);
    gather1_kernel<<<(N_NODES * 32 + 255) / 256, 256>>>(x);
    gemm1_kernel<<<(N_NODES + 127) / 128, 256, SMEM1>>>();
    gemm2_kernel<<<(N_NODES + 127) / 128, 256, SMEM2>>>(W2);
    gather2_kernel<<<(N_NODES * 32 + 255) / 256, 256>>>(b2, out);
}

// round 4
// speedup vs baseline: 2.2756x; 1.4343x over previous
#include <cuda_runtime.h>

#define N_NODES 50000
#define D 128
#define DOUT 64
#define E_EDGES 800000

#define SCAN_BLK 2048                       // elements per scan block
#define SCAN_GRID ((N_NODES + SCAN_BLK - 1) / SCAN_BLK)   // 25

// Scratch (device globals — no allocation allowed)
__device__ __align__(16) float g_agg1[N_NODES * D];
__device__ __align__(16) float g_h1[N_NODES * D];
__device__ __align__(16) float g_h2[N_NODES * DOUT];
__device__ __align__(16) float g_Wc[D * D];
__device__ __align__(16) float g_bc[D];
__device__ int g_rowcnt[N_NODES];
__device__ int g_rowptr[N_NODES + 1];
__device__ int g_cursor[N_NODES];
__device__ int g_csr_src[E_EDGES];
__device__ int g_blocksum[SCAN_GRID];
__device__ int g_blockoff[SCAN_GRID];

// ---------------------------------------------------------------------------
// Prep: Wc = W_pre @ W1, bc = b_pre @ W1 + b1
// ---------------------------------------------------------------------------
__global__ void prep_kernel(const float* __restrict__ W_pre,
                            const float* __restrict__ b_pre,
                            const float* __restrict__ W1,
                            const float* __restrict__ b1) {
    int c = threadIdx.x;
    int r = blockIdx.x;
    if (r < D) {
        float acc = 0.f;
#pragma unroll 8
        for (int k = 0; k < D; k++) acc += W_pre[r * D + k] * W1[k * D + c];
        g_Wc[r * D + c] = acc;
    } else {
        float acc = b1[c];
#pragma unroll 8
        for (int k = 0; k < D; k++) acc += b_pre[k] * W1[k * D + c];
        g_bc[c] = acc;
    }
}

// ---------------------------------------------------------------------------
// CSR build: zero -> histogram -> 3-phase scan -> fill
// ---------------------------------------------------------------------------
__global__ void zero_hist_kernel() {
    int i = blockIdx.x * blockDim.x + threadIdx.x;
    if (i < N_NODES) g_rowcnt[i] = 0;
}

__global__ void hist_kernel(const int* __restrict__ dst) {
    int e = blockIdx.x * blockDim.x + threadIdx.x;
    if (e < E_EDGES) atomicAdd(&g_rowcnt[dst[e]], 1);
}

// Phase 1: per-block exclusive scan (256 threads x 8 elems), emit block totals.
__global__ void scan1_kernel() {
    __shared__ int warpsum[8];
    int t = threadIdx.x;
    int lane = t & 31, warp = t >> 5;
    int base = blockIdx.x * SCAN_BLK + t * 8;

    int v[8], s = 0;
#pragma unroll
    for (int j = 0; j < 8; j++) {
        int i = base + j;
        v[j] = (i < N_NODES) ? g_rowcnt[i] : 0;
        s += v[j];
    }
    // warp inclusive scan of per-thread sums
    int ps = s;
#pragma unroll
    for (int off = 1; off < 32; off <<= 1) {
        int n = __shfl_up_sync(0xffffffffu, ps, off);
        if (lane >= off) ps += n;
    }
    if (lane == 31) warpsum[warp] = ps;
    __syncthreads();
    if (warp == 0) {
        int ws = (lane < 8) ? warpsum[lane] : 0;
#pragma unroll
        for (int off = 1; off < 8; off <<= 1) {
            int n = __shfl_up_sync(0xffffffffu, ws, off);
            if (lane >= off) ws += n;
        }
        if (lane < 8) warpsum[lane] = ws - ((lane < 8) ? ((lane == 0) ? ws : 0) : 0);
        // store exclusive: ws is inclusive; convert below
        if (lane < 8) warpsum[lane] = ws;
    }
    __syncthreads();
    int woff = (warp == 0) ? 0 : warpsum[warp - 1];
    int excl = ps - s + woff;  // exclusive prefix of this thread within block

    int run = excl;
#pragma unroll
    for (int j = 0; j < 8; j++) {
        int i = base + j;
        if (i < N_NODES) g_rowptr[i] = run;
        run += v[j];
    }
    if (t == 255) g_blocksum[blockIdx.x] = run;  // block total
}

// Phase 2: one warp scans the block totals (exclusive).
__global__ void scan2_kernel() {
    int lane = threadIdx.x;
    int v = (lane < SCAN_GRID) ? g_blocksum[lane] : 0;
    int ps = v;
#pragma unroll
    for (int off = 1; off < 32; off <<= 1) {
        int n = __shfl_up_sync(0xffffffffu, ps, off);
        if (lane >= off) ps += n;
    }
    if (lane < SCAN_GRID) g_blockoff[lane] = ps - v;
    if (lane == 0) g_rowptr[N_NODES] = E_EDGES;
}

// Phase 3: add block offsets; seed cursor.
__global__ void scan3_kernel() {
    int off = g_blockoff[blockIdx.x];
    int base = blockIdx.x * SCAN_BLK + threadIdx.x * 8;
#pragma unroll
    for (int j = 0; j < 8; j++) {
        int i = base + j;
        if (i < N_NODES) {
            int p = g_rowptr[i] + off;
            g_rowptr[i] = p;
            g_cursor[i] = p;
        }
    }
}

__global__ void fill_kernel(const int* __restrict__ src,
                            const int* __restrict__ dst) {
    int e = blockIdx.x * blockDim.x + threadIdx.x;
    if (e < E_EDGES) {
        int pos = atomicAdd(&g_cursor[dst[e]], 1);
        g_csr_src[pos] = src[e];
    }
}

// ---------------------------------------------------------------------------
// Gather layer 1: agg1[i] = mean over {i} u in-neighbors of x  (128 dims)
// ---------------------------------------------------------------------------
__global__ void gather1_kernel(const float* __restrict__ x) {
    int node = (blockIdx.x * blockDim.x + threadIdx.x) >> 5;
    int lane = threadIdx.x & 31;
    if (node >= N_NODES) return;
    int beg = g_rowptr[node];
    int end = g_rowptr[node + 1];

    float4 acc = *reinterpret_cast<const float4*>(x + (size_t)node * D + lane * 4);

    for (int base = beg; base < end; base += 32) {
        int idx = 0;
        if (base + lane < end) idx = __ldg(&g_csr_src[base + lane]);
        int m = end - base; if (m > 32) m = 32;
        for (int j = 0; j < m; j++) {
            int s = __shfl_sync(0xffffffffu, idx, j);
            float4 v = *reinterpret_cast<const float4*>(x + (size_t)s * D + lane * 4);
            acc.x += v.x; acc.y += v.y; acc.z += v.z; acc.w += v.w;
        }
    }
    float inv = 1.0f / (float)(end - beg + 1);
    acc.x *= inv; acc.y *= inv; acc.z *= inv; acc.w *= inv;
    *reinterpret_cast<float4*>(g_agg1 + (size_t)node * D + lane * 4) = acc;
}

// ---------------------------------------------------------------------------
// GEMM1: h1 = relu(agg1 @ Wc + bc); 128x128 tile, 8x8 per thread
// ---------------------------------------------------------------------------
#define ISTR (D + 1)
__global__ void gemm1_kernel() {
    extern __shared__ float sm[];
    float* wc = sm;
    float* in = sm + D * D;
    int tid = threadIdx.x;
    int row0 = blockIdx.x * 128;

#pragma unroll
    for (int i = tid; i < D * D; i += 256) wc[i] = g_Wc[i];
#pragma unroll
    for (int i = tid; i < 128 * D; i += 256) {
        int r = i >> 7, k = i & 127;
        int row = row0 + r;
        in[r * ISTR + k] = (row < N_NODES) ? g_agg1[(size_t)row * D + k] : 0.f;
    }
    __syncthreads();

    int ty = tid >> 4, tx = tid & 15;
    float acc[8][8];
#pragma unroll
    for (int i = 0; i < 8; i++)
#pragma unroll
        for (int j = 0; j < 8; j++) acc[i][j] = 0.f;

#pragma unroll 4
    for (int k = 0; k < D; k++) {
        float a[8];
#pragma unroll
        for (int i = 0; i < 8; i++) a[i] = in[(ty * 8 + i) * ISTR + k];
        float4 w0 = *reinterpret_cast<const float4*>(&wc[k * D + tx * 8]);
        float4 w1 = *reinterpret_cast<const float4*>(&wc[k * D + tx * 8 + 4]);
        float w[8] = {w0.x, w0.y, w0.z, w0.w, w1.x, w1.y, w1.z, w1.w};
#pragma unroll
        for (int i = 0; i < 8; i++)
#pragma unroll
            for (int j = 0; j < 8; j++) acc[i][j] += a[i] * w[j];
    }

    int c = tx * 8;
    float4 b0 = *reinterpret_cast<const float4*>(&g_bc[c]);
    float4 b1 = *reinterpret_cast<const float4*>(&g_bc[c + 4]);
#pragma unroll
    for (int i = 0; i < 8; i++) {
        int row = row0 + ty * 8 + i;
        if (row < N_NODES) {
            float4 o0, o1;
            o0.x = fmaxf(acc[i][0] + b0.x, 0.f);
            o0.y = fmaxf(acc[i][1] + b0.y, 0.f);
            o0.z = fmaxf(acc[i][2] + b0.z, 0.f);
            o0.w = fmaxf(acc[i][3] + b0.w, 0.f);
            o1.x = fmaxf(acc[i][4] + b1.x, 0.f);
            o1.y = fmaxf(acc[i][5] + b1.y, 0.f);
            o1.z = fmaxf(acc[i][6] + b1.z, 0.f);
            o1.w = fmaxf(acc[i][7] + b1.w, 0.f);
            *reinterpret_cast<float4*>(&g_h1[(size_t)row * D + c]) = o0;
            *reinterpret_cast<float4*>(&g_h1[(size_t)row * D + c + 4]) = o1;
        }
    }
}

// ---------------------------------------------------------------------------
// GEMM2: h2 = h1 @ W2 (bias deferred to gather2 epilogue)
// ---------------------------------------------------------------------------
__global__ void gemm2_kernel(const float* __restrict__ W2) {
    extern __shared__ float sm[];
    float* w2 = sm;
    float* in = sm + D * DOUT;
    int tid = threadIdx.x;
    int row0 = blockIdx.x * 128;

#pragma unroll
    for (int i = tid; i < D * DOUT; i += 256) w2[i] = W2[i];
#pragma unroll
    for (int i = tid; i < 128 * D; i += 256) {
        int r = i >> 7, k = i & 127;
        int row = row0 + r;
        in[r * ISTR + k] = (row < N_NODES) ? g_h1[(size_t)row * D + k] : 0.f;
    }
    __syncthreads();

    int ty = tid >> 4, tx = tid & 15;
    float acc[8][4];
#pragma unroll
    for (int i = 0; i < 8; i++)
#pragma unroll
        for (int j = 0; j < 4; j++) acc[i][j] = 0.f;

#pragma unroll 4
    for (int k = 0; k < D; k++) {
        float a[8];
#pragma unroll
        for (int i = 0; i < 8; i++) a[i] = in[(ty * 8 + i) * ISTR + k];
        float4 w = *reinterpret_cast<const float4*>(&w2[k * DOUT + tx * 4]);
#pragma unroll
        for (int i = 0; i < 8; i++) {
            acc[i][0] += a[i] * w.x;
            acc[i][1] += a[i] * w.y;
            acc[i][2] += a[i] * w.z;
            acc[i][3] += a[i] * w.w;
        }
    }

    int c = tx * 4;
#pragma unroll
    for (int i = 0; i < 8; i++) {
        int row = row0 + ty * 8 + i;
        if (row < N_NODES) {
            float4 o = make_float4(acc[i][0], acc[i][1], acc[i][2], acc[i][3]);
            *reinterpret_cast<float4*>(&g_h2[(size_t)row * DOUT + c]) = o;
        }
    }
}

// ---------------------------------------------------------------------------
// Gather layer 2 + bias + L2 normalize, fused.  (64 dims)
// ---------------------------------------------------------------------------
__global__ void gather2_kernel(const float* __restrict__ b2,
                               float* __restrict__ out) {
    int node = (blockIdx.x * blockDim.x + threadIdx.x) >> 5;
    int lane = threadIdx.x & 31;
    if (node >= N_NODES) return;
    int beg = g_rowptr[node];
    int end = g_rowptr[node + 1];

    float2 acc = *reinterpret_cast<const float2*>(g_h2 + (size_t)node * DOUT + lane * 2);

    for (int base = beg; base < end; base += 32) {
        int idx = 0;
        if (base + lane < end) idx = __ldg(&g_csr_src[base + lane]);
        int m = end - base; if (m > 32) m = 32;
        for (int j = 0; j < m; j++) {
            int s = __shfl_sync(0xffffffffu, idx, j);
            float2 v = *reinterpret_cast<const float2*>(g_h2 + (size_t)s * DOUT + lane * 2);
            acc.x += v.x; acc.y += v.y;
        }
    }
    float inv = 1.0f / (float)(end - beg + 1);
    float2 b = *reinterpret_cast<const float2*>(b2 + lane * 2);
    float a0 = acc.x * inv + b.x;
    float a1 = acc.y * inv + b.y;
    float ss = a0 * a0 + a1 * a1;
#pragma unroll
    for (int o = 16; o; o >>= 1) ss += __shfl_xor_sync(0xffffffffu, ss, o);
    float s = 1.0f / fmaxf(sqrtf(ss), 1e-12f);
    float2 o2 = make_float2(a0 * s, a1 * s);
    *reinterpret_cast<float2*>(&out[(size_t)node * DOUT + lane * 2]) = o2;
}

// ---------------------------------------------------------------------------
extern "C" void kernel_launch(void* const* d_in, const int* in_sizes, int n_in,
                              void* d_out, int out_size) {
    const float* x     = (const float*)d_in[0];
    const int*   ei    = (const int*)d_in[1];
    const float* W_pre = (const float*)d_in[2];
    const float* b_pre = (const float*)d_in[3];
    const float* W1    = (const float*)d_in[4];
    const float* b1    = (const float*)d_in[5];
    const float* W2    = (const float*)d_in[6];
    const float* b2    = (const float*)d_in[7];
    float* out = (float*)d_out;

    const int* src = ei;
    const int* dst = ei + E_EDGES;

    const int SMEM1 = (D * D + 128 * ISTR) * 4;
    const int SMEM2 = (D * DOUT + 128 * ISTR) * 4;
    static bool attr_set = false;
    if (!attr_set) {
        cudaFuncSetAttribute(gemm1_kernel, cudaFuncAttributeMaxDynamicSharedMemorySize, SMEM1);
        cudaFuncSetAttribute(gemm2_kernel, cudaFuncAttributeMaxDynamicSharedMemorySize, SMEM2);
        attr_set = true;
    }

    prep_kernel<<<D + 1, D>>>(W_pre, b_pre, W1, b1);
    zero_hist_kernel<<<(N_NODES + 255) / 256, 256>>>();
    hist_kernel<<<(E_EDGES + 255) / 256, 256>>>(dst);
    scan1_kernel<<<SCAN_GRID, 256>>>();
    scan2_kernel<<<1, 32>>>();
    scan3_kernel<<<SCAN_GRID, 256>>>();
    fill_kernel<<<(E_EDGES + 255) / 256, 256>>>(src, dst);
    gather1_kernel<<<(N_NODES * 32 + 255) / 256, 256>>>(x);
    gemm1_kernel<<<(N_NODES + 127) / 128, 256, SMEM1>>>();
    gemm2_kernel<<<(N_NODES + 127) / 128, 256, SMEM2>>>(W2);
    gather2_kernel<<<(N_NODES * 32 + 255) / 256, 256>>>(b2, out);
}

// round 6
// speedup vs baseline: 2.5008x; 1.0990x over previous
#include <cuda_runtime.h>
#include <cstdint>

#define N_NODES 50000
#define D 128
#define DOUT 64
#define E_EDGES 800000

#define SCAN_BLK 2048
#define SCAN_GRID ((N_NODES + SCAN_BLK - 1) / SCAN_BLK)   // 25

// ---------------- device globals (no allocation allowed) ----------------
__device__ __align__(16) float g_agg1[N_NODES * D];
__device__ __align__(16) float g_h2[N_NODES * DOUT];
__device__ __align__(16) float g_bc[D];
__device__ int g_rowcnt[N_NODES];
__device__ int g_rowptr[N_NODES + 1];
__device__ int g_cursor[N_NODES];
__device__ int g_csr_src[E_EDGES];
__device__ int g_blocksum[SCAN_GRID];
// tf32 split weight images, transposed: [out_col][k], fp32 storage of tf32 values
__device__ __align__(16) float g_WcT_h[D * D];
__device__ __align__(16) float g_WcT_l[D * D];
__device__ __align__(16) float g_W2T_h[DOUT * D];
__device__ __align__(16) float g_W2T_l[DOUT * D];

// ---------------- tf32 helpers ----------------
__device__ __forceinline__ uint32_t f2tf32(float f) {
    uint32_t r;
    asm("cvt.rna.tf32.f32 %0, %1;" : "=r"(r) : "f"(f));
    return r;
}

__device__ __forceinline__ void split_tf32(float a, uint32_t& hi, uint32_t& lo) {
    hi = f2tf32(a);
    lo = f2tf32(a - __uint_as_float(hi));
}

__device__ __forceinline__ void mma_tf32(float* d, const uint32_t* a,
                                         uint32_t b0, uint32_t b1) {
    asm volatile(
        "mma.sync.aligned.m16n8k8.row.col.f32.tf32.tf32.f32 "
        "{%0,%1,%2,%3}, {%4,%5,%6,%7}, {%8,%9}, {%0,%1,%2,%3};"
        : "+f"(d[0]), "+f"(d[1]), "+f"(d[2]), "+f"(d[3])
        : "r"(a[0]), "r"(a[1]), "r"(a[2]), "r"(a[3]), "r"(b0), "r"(b1));
}

// ---------------------------------------------------------------------------
// Prep: Wc = W_pre @ W1 -> tf32 hi/lo transposed images; bc = b_pre @ W1 + b1
// ---------------------------------------------------------------------------
__global__ void prep_kernel(const float* __restrict__ W_pre,
                            const float* __restrict__ b_pre,
                            const float* __restrict__ W1,
                            const float* __restrict__ b1) {
    int c = threadIdx.x;
    int r = blockIdx.x;
    if (r < D) {
        float acc = 0.f;
#pragma unroll 8
        for (int k = 0; k < D; k++) acc += W_pre[r * D + k] * W1[k * D + c];
        uint32_t hi, lo;
        split_tf32(acc, hi, lo);
        g_WcT_h[c * D + r] = __uint_as_float(hi);
        g_WcT_l[c * D + r] = __uint_as_float(lo);
    } else {
        float acc = b1[c];
#pragma unroll 8
        for (int k = 0; k < D; k++) acc += b_pre[k] * W1[k * D + c];
        g_bc[c] = acc;
    }
}

__global__ void prepw2_kernel(const float* __restrict__ W2) {
    int k = threadIdx.x;   // 0..127
    int n = blockIdx.x;    // 0..63
    uint32_t hi, lo;
    split_tf32(W2[k * DOUT + n], hi, lo);
    g_W2T_h[n * D + k] = __uint_as_float(hi);
    g_W2T_l[n * D + k] = __uint_as_float(lo);
}

// ---------------------------------------------------------------------------
// CSR build
// ---------------------------------------------------------------------------
__global__ void zero_hist_kernel() {
    int i = blockIdx.x * blockDim.x + threadIdx.x;
    if (i < N_NODES) g_rowcnt[i] = 0;
}

__global__ void hist_kernel(const int* __restrict__ dst) {
    int e = blockIdx.x * blockDim.x + threadIdx.x;
    if (e < E_EDGES) atomicAdd(&g_rowcnt[dst[e]], 1);
}

__global__ void scan1_kernel() {
    __shared__ int warpsum[8];
    int t = threadIdx.x;
    int lane = t & 31, warp = t >> 5;
    int base = blockIdx.x * SCAN_BLK + t * 8;

    int v[8], s = 0;
#pragma unroll
    for (int j = 0; j < 8; j++) {
        int i = base + j;
        v[j] = (i < N_NODES) ? g_rowcnt[i] : 0;
        s += v[j];
    }
    int ps = s;
#pragma unroll
    for (int off = 1; off < 32; off <<= 1) {
        int n = __shfl_up_sync(0xffffffffu, ps, off);
        if (lane >= off) ps += n;
    }
    if (lane == 31) warpsum[warp] = ps;
    __syncthreads();
    if (warp == 0 && lane < 8) {
        int ws = warpsum[lane];
#pragma unroll
        for (int off = 1; off < 8; off <<= 1) {
            int n = __shfl_up_sync(0x000000ffu, ws, off);
            if (lane >= off) ws += n;
        }
        warpsum[lane] = ws;
    }
    __syncthreads();
    int woff = (warp == 0) ? 0 : warpsum[warp - 1];
    int run = ps - s + woff;
#pragma unroll
    for (int j = 0; j < 8; j++) {
        int i = base + j;
        if (i < N_NODES) g_rowptr[i] = run;
        run += v[j];
    }
    if (t == 255) g_blocksum[blockIdx.x] = run;
}

// scan3 with inline block-total scan
__global__ void scan3_kernel() {
    __shared__ int s_off;
    if (threadIdx.x < 32) {
        int lane = threadIdx.x;
        int v = (lane < SCAN_GRID) ? g_blocksum[lane] : 0;
        int ps = v;
#pragma unroll
        for (int off = 1; off < 32; off <<= 1) {
            int n = __shfl_up_sync(0xffffffffu, ps, off);
            if (lane >= off) ps += n;
        }
        if (lane == (int)blockIdx.x) s_off = ps - v;
        if (blockIdx.x == SCAN_GRID - 1 && lane == SCAN_GRID - 1)
            g_rowptr[N_NODES] = ps;
    }
    __syncthreads();
    int off = s_off;
    int base = blockIdx.x * SCAN_BLK + threadIdx.x * 8;
#pragma unroll
    for (int j = 0; j < 8; j++) {
        int i = base + j;
        if (i < N_NODES) {
            int p = g_rowptr[i] + off;
            g_rowptr[i] = p;
            g_cursor[i] = p;
        }
    }
}

__global__ void fill_kernel(const int* __restrict__ src,
                            const int* __restrict__ dst) {
    int e = blockIdx.x * blockDim.x + threadIdx.x;
    if (e < E_EDGES) {
        int pos = atomicAdd(&g_cursor[dst[e]], 1);
        g_csr_src[pos] = src[e];
    }
}

// ---------------------------------------------------------------------------
// Gather layer 1 (fp32, 128 dims, warp per node)
// ---------------------------------------------------------------------------
__global__ void gather1_kernel(const float* __restrict__ x) {
    int node = (blockIdx.x * blockDim.x + threadIdx.x) >> 5;
    int lane = threadIdx.x & 31;
    if (node >= N_NODES) return;
    int beg = g_rowptr[node];
    int end = g_rowptr[node + 1];

    float4 acc = *reinterpret_cast<const float4*>(x + (size_t)node * D + lane * 4);

    for (int base = beg; base < end; base += 32) {
        int idx = 0;
        if (base + lane < end) idx = __ldg(&g_csr_src[base + lane]);
        int m = end - base; if (m > 32) m = 32;
        for (int j = 0; j < m; j++) {
            int s = __shfl_sync(0xffffffffu, idx, j);
            float4 v = *reinterpret_cast<const float4*>(x + (size_t)s * D + lane * 4);
            acc.x += v.x; acc.y += v.y; acc.z += v.z; acc.w += v.w;
        }
    }
    float inv = 1.0f / (float)(end - beg + 1);
    acc.x *= inv; acc.y *= inv; acc.z *= inv; acc.w *= inv;
    *reinterpret_cast<float4*>(g_agg1 + (size_t)node * D + lane * 4) = acc;
}

// ---------------------------------------------------------------------------
// Fused GEMM via mma.sync tf32 (3xTF32 split):
//   h2 = relu(agg1 @ Wc + bc) @ W2
// 256 threads, 128-row tile. Warp w: rows (w>>1)*32..+31, cols (w&1)*{64|32}.
// ---------------------------------------------------------------------------
#define ASTR 132
#define FG_SMEM ((D + 128 * ASTR + 2 * 128 * ASTR) * 4)   // bias + A + Wh + Wl

__global__ void __launch_bounds__(256, 1) fusedgemm_kernel() {
    extern __shared__ float sm[];
    float* bias = sm;                    // 128
    float* sA   = sm + D;                // 128 x ASTR (fp32)
    float* sWh  = sA + 128 * ASTR;       // 128 x ASTR
    float* sWl  = sWh + 128 * ASTR;      // 128 x ASTR

    int tid = threadIdx.x;
    int w = tid >> 5, lane = tid & 31;
    int g = lane >> 2, qi = lane & 3;
    int row0 = blockIdx.x * 128;

    if (tid < D) bias[tid] = g_bc[tid];
    // A tile (fp32)
    for (int i = tid; i < 128 * 32; i += 256) {
        int r = i >> 5, c4 = (i & 31) << 2;
        float4 v = make_float4(0.f, 0.f, 0.f, 0.f);
        int row = row0 + r;
        if (row < N_NODES) v = *reinterpret_cast<const float4*>(g_agg1 + (size_t)row * D + c4);
        *reinterpret_cast<float4*>(&sA[r * ASTR + c4]) = v;
    }
    // Wc hi/lo images (transposed [n][k])
    for (int i = tid; i < 128 * 32; i += 256) {
        int r = i >> 5, c4 = (i & 31) << 2;
        *reinterpret_cast<float4*>(&sWh[r * ASTR + c4]) =
            *reinterpret_cast<const float4*>(&g_WcT_h[r * D + c4]);
        *reinterpret_cast<float4*>(&sWl[r * ASTR + c4]) =
            *reinterpret_cast<const float4*>(&g_WcT_l[r * D + c4]);
    }
    __syncthreads();

    // ---- layer 1: 128x128 output, warp tile 32 rows x 64 cols ----
    int rw0 = (w >> 1) * 32;
    int cw0 = (w & 1) * 64;
    float acc[2][8][4];
#pragma unroll
    for (int mt = 0; mt < 2; mt++)
#pragma unroll
        for (int nt = 0; nt < 8; nt++)
#pragma unroll
            for (int j = 0; j < 4; j++) acc[mt][nt][j] = 0.f;

#pragma unroll 4
    for (int ks = 0; ks < 16; ks++) {
        int k0 = ks * 8;
        uint32_t ah[2][4], al[2][4];
#pragma unroll
        for (int mt = 0; mt < 2; mt++) {
            int rb = rw0 + mt * 16;
            float f0 = sA[(rb + g) * ASTR + k0 + qi];
            float f1 = sA[(rb + g + 8) * ASTR + k0 + qi];
            float f2 = sA[(rb + g) * ASTR + k0 + qi + 4];
            float f3 = sA[(rb + g + 8) * ASTR + k0 + qi + 4];
            split_tf32(f0, ah[mt][0], al[mt][0]);
            split_tf32(f1, ah[mt][1], al[mt][1]);
            split_tf32(f2, ah[mt][2], al[mt][2]);
            split_tf32(f3, ah[mt][3], al[mt][3]);
        }
#pragma unroll
        for (int nt = 0; nt < 8; nt++) {
            int nb = cw0 + nt * 8;
            uint32_t bh0 = __float_as_uint(sWh[(nb + g) * ASTR + k0 + qi]);
            uint32_t bh1 = __float_as_uint(sWh[(nb + g) * ASTR + k0 + qi + 4]);
            uint32_t bl0 = __float_as_uint(sWl[(nb + g) * ASTR + k0 + qi]);
            uint32_t bl1 = __float_as_uint(sWl[(nb + g) * ASTR + k0 + qi + 4]);
#pragma unroll
            for (int mt = 0; mt < 2; mt++) {
                mma_tf32(acc[mt][nt], ah[mt], bh0, bh1);
                mma_tf32(acc[mt][nt], ah[mt], bl0, bl1);
                mma_tf32(acc[mt][nt], al[mt], bh0, bh1);
            }
        }
    }
    __syncthreads();

    // ---- epilogue 1: bias + relu -> h1 back into sA ----
#pragma unroll
    for (int mt = 0; mt < 2; mt++) {
        int rb = rw0 + mt * 16;
#pragma unroll
        for (int nt = 0; nt < 8; nt++) {
            int c0 = cw0 + nt * 8 + qi * 2;
            float b0 = bias[c0], b1 = bias[c0 + 1];
            sA[(rb + g) * ASTR + c0]         = fmaxf(acc[mt][nt][0] + b0, 0.f);
            sA[(rb + g) * ASTR + c0 + 1]     = fmaxf(acc[mt][nt][1] + b1, 0.f);
            sA[(rb + g + 8) * ASTR + c0]     = fmaxf(acc[mt][nt][2] + b0, 0.f);
            sA[(rb + g + 8) * ASTR + c0 + 1] = fmaxf(acc[mt][nt][3] + b1, 0.f);
        }
    }
    __syncthreads();

    // ---- load W2 hi/lo images (overwrite Wc region) ----
    float* sW2h = sWh;
    float* sW2l = sWh + DOUT * ASTR;
    for (int i = tid; i < DOUT * 32; i += 256) {
        int r = i >> 5, c4 = (i & 31) << 2;
        *reinterpret_cast<float4*>(&sW2h[r * ASTR + c4]) =
            *reinterpret_cast<const float4*>(&g_W2T_h[r * D + c4]);
        *reinterpret_cast<float4*>(&sW2l[r * ASTR + c4]) =
            *reinterpret_cast<const float4*>(&g_W2T_l[r * D + c4]);
    }
    __syncthreads();

    // ---- layer 2: 128x64 output, warp tile 32 rows x 32 cols ----
    int cw2 = (w & 1) * 32;
    float acc2[2][4][4];
#pragma unroll
    for (int mt = 0; mt < 2; mt++)
#pragma unroll
        for (int nt = 0; nt < 4; nt++)
#pragma unroll
            for (int j = 0; j < 4; j++) acc2[mt][nt][j] = 0.f;

#pragma unroll 4
    for (int ks = 0; ks < 16; ks++) {
        int k0 = ks * 8;
        uint32_t ah[2][4], al[2][4];
#pragma unroll
        for (int mt = 0; mt < 2; mt++) {
            int rb = rw0 + mt * 16;
            float f0 = sA[(rb + g) * ASTR + k0 + qi];
            float f1 = sA[(rb + g + 8) * ASTR + k0 + qi];
            float f2 = sA[(rb + g) * ASTR + k0 + qi + 4];
            float f3 = sA[(rb + g + 8) * ASTR + k0 + qi + 4];
            split_tf32(f0, ah[mt][0], al[mt][0]);
            split_tf32(f1, ah[mt][1], al[mt][1]);
            split_tf32(f2, ah[mt][2], al[mt][2]);
            split_tf32(f3, ah[mt][3], al[mt][3]);
        }
#pragma unroll
        for (int nt = 0; nt < 4; nt++) {
            int nb = cw2 + nt * 8;
            uint32_t bh0 = __float_as_uint(sW2h[(nb + g) * ASTR + k0 + qi]);
            uint32_t bh1 = __float_as_uint(sW2h[(nb + g) * ASTR + k0 + qi + 4]);
            uint32_t bl0 = __float_as_uint(sW2l[(nb + g) * ASTR + k0 + qi]);
            uint32_t bl1 = __float_as_uint(sW2l[(nb + g) * ASTR + k0 + qi + 4]);
#pragma unroll
            for (int mt = 0; mt < 2; mt++) {
                mma_tf32(acc2[mt][nt], ah[mt], bh0, bh1);
                mma_tf32(acc2[mt][nt], ah[mt], bl0, bl1);
                mma_tf32(acc2[mt][nt], al[mt], bh0, bh1);
            }
        }
    }
    __syncthreads();

    // ---- epilogue 2: stage h2 in smem (stride 66), coalesced store ----
    float* h2s = sA;
#pragma unroll
    for (int mt = 0; mt < 2; mt++) {
        int rb = rw0 + mt * 16;
#pragma unroll
        for (int nt = 0; nt < 4; nt++) {
            int c0 = cw2 + nt * 8 + qi * 2;
            h2s[(rb + g) * 66 + c0]         = acc2[mt][nt][0];
            h2s[(rb + g) * 66 + c0 + 1]     = acc2[mt][nt][1];
            h2s[(rb + g + 8) * 66 + c0]     = acc2[mt][nt][2];
            h2s[(rb + g + 8) * 66 + c0 + 1] = acc2[mt][nt][3];
        }
    }
    __syncthreads();
    for (int i = tid; i < 128 * 32; i += 256) {
        int r = i >> 5, c2 = (i & 31) << 1;
        int row = row0 + r;
        if (row < N_NODES) {
            float2 v = *reinterpret_cast<const float2*>(&h2s[r * 66 + c2]);
            *reinterpret_cast<float2*>(&g_h2[(size_t)row * DOUT + c2]) = v;
        }
    }
}

// ---------------------------------------------------------------------------
// Gather layer 2 + bias + L2 normalize, fused. (64 dims)
// ---------------------------------------------------------------------------
__global__ void gather2_kernel(const float* __restrict__ b2,
                               float* __restrict__ out) {
    int node = (blockIdx.x * blockDim.x + threadIdx.x) >> 5;
    int lane = threadIdx.x & 31;
    if (node >= N_NODES) return;
    int beg = g_rowptr[node];
    int end = g_rowptr[node + 1];

    float2 acc = *reinterpret_cast<const float2*>(g_h2 + (size_t)node * DOUT + lane * 2);

    for (int base = beg; base < end; base += 32) {
        int idx = 0;
        if (base + lane < end) idx = __ldg(&g_csr_src[base + lane]);
        int m = end - base; if (m > 32) m = 32;
        for (int j = 0; j < m; j++) {
            int s = __shfl_sync(0xffffffffu, idx, j);
            float2 v = *reinterpret_cast<const float2*>(g_h2 + (size_t)s * DOUT + lane * 2);
            acc.x += v.x; acc.y += v.y;
        }
    }
    float inv = 1.0f / (float)(end - beg + 1);
    float2 b = *reinterpret_cast<const float2*>(b2 + lane * 2);
    float a0 = acc.x * inv + b.x;
    float a1 = acc.y * inv + b.y;
    float ss = a0 * a0 + a1 * a1;
#pragma unroll
    for (int o = 16; o; o >>= 1) ss += __shfl_xor_sync(0xffffffffu, ss, o);
    float s = 1.0f / fmaxf(sqrtf(ss), 1e-12f);
    float2 o2 = make_float2(a0 * s, a1 * s);
    *reinterpret_cast<float2*>(&out[(size_t)node * DOUT + lane * 2]) = o2;
}

// ---------------------------------------------------------------------------
extern "C" void kernel_launch(void* const* d_in, const int* in_sizes, int n_in,
                              void* d_out, int out_size) {
    const float* x     = (const float*)d_in[0];
    const int*   ei    = (const int*)d_in[1];
    const float* W_pre = (const float*)d_in[2];
    const float* b_pre = (const float*)d_in[3];
    const float* W1    = (const float*)d_in[4];
    const float* b1    = (const float*)d_in[5];
    const float* W2    = (const float*)d_in[6];
    const float* b2    = (const float*)d_in[7];
    float* out = (float*)d_out;

    const int* src = ei;
    const int* dst = ei + E_EDGES;

    static bool attr_set = false;
    if (!attr_set) {
        cudaFuncSetAttribute(fusedgemm_kernel,
                             cudaFuncAttributeMaxDynamicSharedMemorySize, FG_SMEM);
        attr_set = true;
    }

    prep_kernel<<<D + 1, D>>>(W_pre, b_pre, W1, b1);
    prepw2_kernel<<<DOUT, D>>>(W2);
    zero_hist_kernel<<<(N_NODES + 255) / 256, 256>>>();
    hist_kernel<<<(E_EDGES + 255) / 256, 256>>>(dst);
    scan1_kernel<<<SCAN_GRID, 256>>>();
    scan3_kernel<<<SCAN_GRID, 256>>>();
    fill_kernel<<<(E_EDGES + 255) / 256, 256>>>(src, dst);
    gather1_kernel<<<(N_NODES * 32 + 255) / 256, 256>>>(x);
    fusedgemm_kernel<<<(N_NODES + 127) / 128, 256, FG_SMEM>>>();
    gather2_kernel<<<(N_NODES * 32 + 255) / 256, 256>>>(b2, out);
}

// round 7
// speedup vs baseline: 2.6683x; 1.0670x over previous
#include <cuda_runtime.h>
#include <cstdint>

#define N_NODES 50000
#define D 128
#define DOUT 64
#define E_EDGES 800000

#define SCAN_BLK 2048
#define SCAN_GRID ((N_NODES + SCAN_BLK - 1) / SCAN_BLK)   // 25

// ---------------- device globals (no allocation allowed) ----------------
__device__ __align__(16) float g_agg1[N_NODES * D];
__device__ __align__(16) float g_h2[N_NODES * DOUT];
__device__ __align__(16) float g_bc[D];
__device__ int g_rowcnt[N_NODES];
__device__ int g_rowptr[N_NODES + 1];
__device__ int g_cursor[N_NODES];
__device__ int g_csr_src[E_EDGES];
__device__ int g_blocksum[SCAN_GRID];
// tf32 split weight images, transposed: [out_col][k]
__device__ __align__(16) float g_WcT_h[D * D];
__device__ __align__(16) float g_WcT_l[D * D];
__device__ __align__(16) float g_W2T_h[DOUT * D];
__device__ __align__(16) float g_W2T_l[DOUT * D];

// ---------------- tf32 helpers ----------------
__device__ __forceinline__ uint32_t f2tf32(float f) {
    uint32_t r;
    asm("cvt.rna.tf32.f32 %0, %1;" : "=r"(r) : "f"(f));
    return r;
}

__device__ __forceinline__ void split_tf32(float a, uint32_t& hi, uint32_t& lo) {
    hi = f2tf32(a);
    lo = f2tf32(a - __uint_as_float(hi));
}

__device__ __forceinline__ void mma_tf32(float* d, const uint32_t* a,
                                         uint32_t b0, uint32_t b1) {
    asm volatile(
        "mma.sync.aligned.m16n8k8.row.col.f32.tf32.tf32.f32 "
        "{%0,%1,%2,%3}, {%4,%5,%6,%7}, {%8,%9}, {%0,%1,%2,%3};"
        : "+f"(d[0]), "+f"(d[1]), "+f"(d[2]), "+f"(d[3])
        : "r"(a[0]), "r"(a[1]), "r"(a[2]), "r"(a[3]), "r"(b0), "r"(b1));
}

// ---------------------------------------------------------------------------
// Merged prep:
//   blocks [0..D-1]   : Wc row r -> tf32 hi/lo transposed images
//   block  D          : bc
//   blocks [D+1 .. D+DOUT] : W2 col n -> tf32 hi/lo transposed images
// ---------------------------------------------------------------------------
__global__ void prep_kernel(const float* __restrict__ W_pre,
                            const float* __restrict__ b_pre,
                            const float* __restrict__ W1,
                            const float* __restrict__ b1,
                            const float* __restrict__ W2) {
    int c = threadIdx.x;
    int r = blockIdx.x;
    if (r < D) {
        float acc = 0.f;
#pragma unroll 8
        for (int k = 0; k < D; k++) acc += W_pre[r * D + k] * W1[k * D + c];
        uint32_t hi, lo;
        split_tf32(acc, hi, lo);
        g_WcT_h[c * D + r] = __uint_as_float(hi);
        g_WcT_l[c * D + r] = __uint_as_float(lo);
    } else if (r == D) {
        float acc = b1[c];
#pragma unroll 8
        for (int k = 0; k < D; k++) acc += b_pre[k] * W1[k * D + c];
        g_bc[c] = acc;
    } else {
        int n = r - D - 1;      // 0..63
        int k = c;              // 0..127
        uint32_t hi, lo;
        split_tf32(W2[k * DOUT + n], hi, lo);
        g_W2T_h[n * D + k] = __uint_as_float(hi);
        g_W2T_l[n * D + k] = __uint_as_float(lo);
    }
}

// ---------------------------------------------------------------------------
// CSR build
// ---------------------------------------------------------------------------
__global__ void hist_kernel(const int* __restrict__ dst) {
    int e = blockIdx.x * blockDim.x + threadIdx.x;
    if (e < E_EDGES) atomicAdd(&g_rowcnt[dst[e]], 1);
}

__global__ void scan1_kernel() {
    __shared__ int warpsum[8];
    int t = threadIdx.x;
    int lane = t & 31, warp = t >> 5;
    int base = blockIdx.x * SCAN_BLK + t * 8;

    int v[8], s = 0;
#pragma unroll
    for (int j = 0; j < 8; j++) {
        int i = base + j;
        v[j] = (i < N_NODES) ? g_rowcnt[i] : 0;
        s += v[j];
    }
    int ps = s;
#pragma unroll
    for (int off = 1; off < 32; off <<= 1) {
        int n = __shfl_up_sync(0xffffffffu, ps, off);
        if (lane >= off) ps += n;
    }
    if (lane == 31) warpsum[warp] = ps;
    __syncthreads();
    if (warp == 0 && lane < 8) {
        int ws = warpsum[lane];
#pragma unroll
        for (int off = 1; off < 8; off <<= 1) {
            int n = __shfl_up_sync(0x000000ffu, ws, off);
            if (lane >= off) ws += n;
        }
        warpsum[lane] = ws;
    }
    __syncthreads();
    int woff = (warp == 0) ? 0 : warpsum[warp - 1];
    int run = ps - s + woff;
#pragma unroll
    for (int j = 0; j < 8; j++) {
        int i = base + j;
        if (i < N_NODES) g_rowptr[i] = run;
        run += v[j];
    }
    if (t == 255) g_blocksum[blockIdx.x] = run;
}

__global__ void scan3_kernel() {
    __shared__ int s_off;
    if (threadIdx.x < 32) {
        int lane = threadIdx.x;
        int v = (lane < SCAN_GRID) ? g_blocksum[lane] : 0;
        int ps = v;
#pragma unroll
        for (int off = 1; off < 32; off <<= 1) {
            int n = __shfl_up_sync(0xffffffffu, ps, off);
            if (lane >= off) ps += n;
        }
        if (lane == (int)blockIdx.x) s_off = ps - v;
        if (blockIdx.x == SCAN_GRID - 1 && lane == SCAN_GRID - 1)
            g_rowptr[N_NODES] = ps;
    }
    __syncthreads();
    int off = s_off;
    int base = blockIdx.x * SCAN_BLK + threadIdx.x * 8;
#pragma unroll
    for (int j = 0; j < 8; j++) {
        int i = base + j;
        if (i < N_NODES) {
            int p = g_rowptr[i] + off;
            g_rowptr[i] = p;
            g_cursor[i] = p;
        }
    }
}

__global__ void fill_kernel(const int* __restrict__ src,
                            const int* __restrict__ dst) {
    int e = blockIdx.x * blockDim.x + threadIdx.x;
    if (e < E_EDGES) {
        int pos = atomicAdd(&g_cursor[dst[e]], 1);
        g_csr_src[pos] = src[e];
    }
}

// ---------------------------------------------------------------------------
// Gather layer 1 (fp32, 128 dims, warp per node) — 4x unrolled inner loop
// ---------------------------------------------------------------------------
__global__ void gather1_kernel(const float* __restrict__ x) {
    int node = (blockIdx.x * blockDim.x + threadIdx.x) >> 5;
    int lane = threadIdx.x & 31;
    if (node >= N_NODES) return;
    int beg = g_rowptr[node];
    int end = g_rowptr[node + 1];

    float4 acc = *reinterpret_cast<const float4*>(x + (size_t)node * D + lane * 4);

    for (int base = beg; base < end; base += 32) {
        int idx = 0;
        if (base + lane < end) idx = __ldg(&g_csr_src[base + lane]);
        int m = end - base; if (m > 32) m = 32;
        int j = 0;
        for (; j + 4 <= m; j += 4) {
            int s0 = __shfl_sync(0xffffffffu, idx, j);
            int s1 = __shfl_sync(0xffffffffu, idx, j + 1);
            int s2 = __shfl_sync(0xffffffffu, idx, j + 2);
            int s3 = __shfl_sync(0xffffffffu, idx, j + 3);
            float4 v0 = *reinterpret_cast<const float4*>(x + (size_t)s0 * D + lane * 4);
            float4 v1 = *reinterpret_cast<const float4*>(x + (size_t)s1 * D + lane * 4);
            float4 v2 = *reinterpret_cast<const float4*>(x + (size_t)s2 * D + lane * 4);
            float4 v3 = *reinterpret_cast<const float4*>(x + (size_t)s3 * D + lane * 4);
            acc.x += (v0.x + v1.x) + (v2.x + v3.x);
            acc.y += (v0.y + v1.y) + (v2.y + v3.y);
            acc.z += (v0.z + v1.z) + (v2.z + v3.z);
            acc.w += (v0.w + v1.w) + (v2.w + v3.w);
        }
        for (; j < m; j++) {
            int s = __shfl_sync(0xffffffffu, idx, j);
            float4 v = *reinterpret_cast<const float4*>(x + (size_t)s * D + lane * 4);
            acc.x += v.x; acc.y += v.y; acc.z += v.z; acc.w += v.w;
        }
    }
    float inv = 1.0f / (float)(end - beg + 1);
    acc.x *= inv; acc.y *= inv; acc.z *= inv; acc.w *= inv;
    *reinterpret_cast<float4*>(g_agg1 + (size_t)node * D + lane * 4) = acc;
}

// ---------------------------------------------------------------------------
// Fused GEMM via mma.sync tf32 (3xTF32 split), 512 threads / 128-row tile
//   layer1 warp tile 32x32 (mt2,nt4); layer2 warp tile 32x16 (mt2,nt2)
// ---------------------------------------------------------------------------
#define ASTR 132
#define FG_SMEM ((D + 128 * ASTR + 2 * 128 * ASTR) * 4)

__global__ void __launch_bounds__(512, 1) fusedgemm_kernel() {
    extern __shared__ float sm[];
    float* bias = sm;                    // 128
    float* sA   = sm + D;                // 128 x ASTR (fp32)
    float* sWh  = sA + 128 * ASTR;       // 128 x ASTR
    float* sWl  = sWh + 128 * ASTR;      // 128 x ASTR

    int tid = threadIdx.x;
    int w = tid >> 5, lane = tid & 31;
    int g = lane >> 2, qi = lane & 3;
    int row0 = blockIdx.x * 128;

    if (tid < D) bias[tid] = g_bc[tid];
    for (int i = tid; i < 128 * 32; i += 512) {
        int r = i >> 5, c4 = (i & 31) << 2;
        float4 v = make_float4(0.f, 0.f, 0.f, 0.f);
        int row = row0 + r;
        if (row < N_NODES) v = *reinterpret_cast<const float4*>(g_agg1 + (size_t)row * D + c4);
        *reinterpret_cast<float4*>(&sA[r * ASTR + c4]) = v;
    }
    for (int i = tid; i < 128 * 32; i += 512) {
        int r = i >> 5, c4 = (i & 31) << 2;
        *reinterpret_cast<float4*>(&sWh[r * ASTR + c4]) =
            *reinterpret_cast<const float4*>(&g_WcT_h[r * D + c4]);
        *reinterpret_cast<float4*>(&sWl[r * ASTR + c4]) =
            *reinterpret_cast<const float4*>(&g_WcT_l[r * D + c4]);
    }
    __syncthreads();

    // ---- layer 1: warp tile 32 rows x 32 cols ----
    int rw0 = (w >> 2) * 32;
    int cw0 = (w & 3) * 32;
    float acc[2][4][4];
#pragma unroll
    for (int mt = 0; mt < 2; mt++)
#pragma unroll
        for (int nt = 0; nt < 4; nt++)
#pragma unroll
            for (int j = 0; j < 4; j++) acc[mt][nt][j] = 0.f;

#pragma unroll 4
    for (int ks = 0; ks < 16; ks++) {
        int k0 = ks * 8;
        uint32_t ah[2][4], al[2][4];
#pragma unroll
        for (int mt = 0; mt < 2; mt++) {
            int rb = rw0 + mt * 16;
            float f0 = sA[(rb + g) * ASTR + k0 + qi];
            float f1 = sA[(rb + g + 8) * ASTR + k0 + qi];
            float f2 = sA[(rb + g) * ASTR + k0 + qi + 4];
            float f3 = sA[(rb + g + 8) * ASTR + k0 + qi + 4];
            split_tf32(f0, ah[mt][0], al[mt][0]);
            split_tf32(f1, ah[mt][1], al[mt][1]);
            split_tf32(f2, ah[mt][2], al[mt][2]);
            split_tf32(f3, ah[mt][3], al[mt][3]);
        }
#pragma unroll
        for (int nt = 0; nt < 4; nt++) {
            int nb = cw0 + nt * 8;
            uint32_t bh0 = __float_as_uint(sWh[(nb + g) * ASTR + k0 + qi]);
            uint32_t bh1 = __float_as_uint(sWh[(nb + g) * ASTR + k0 + qi + 4]);
            uint32_t bl0 = __float_as_uint(sWl[(nb + g) * ASTR + k0 + qi]);
            uint32_t bl1 = __float_as_uint(sWl[(nb + g) * ASTR + k0 + qi + 4]);
#pragma unroll
            for (int mt = 0; mt < 2; mt++) {
                mma_tf32(acc[mt][nt], ah[mt], bh0, bh1);
                mma_tf32(acc[mt][nt], ah[mt], bl0, bl1);
                mma_tf32(acc[mt][nt], al[mt], bh0, bh1);
            }
        }
    }
    __syncthreads();

    // ---- epilogue 1: bias + relu -> h1 back into sA ----
#pragma unroll
    for (int mt = 0; mt < 2; mt++) {
        int rb = rw0 + mt * 16;
#pragma unroll
        for (int nt = 0; nt < 4; nt++) {
            int c0 = cw0 + nt * 8 + qi * 2;
            float b0 = bias[c0], b1 = bias[c0 + 1];
            sA[(rb + g) * ASTR + c0]         = fmaxf(acc[mt][nt][0] + b0, 0.f);
            sA[(rb + g) * ASTR + c0 + 1]     = fmaxf(acc[mt][nt][1] + b1, 0.f);
            sA[(rb + g + 8) * ASTR + c0]     = fmaxf(acc[mt][nt][2] + b0, 0.f);
            sA[(rb + g + 8) * ASTR + c0 + 1] = fmaxf(acc[mt][nt][3] + b1, 0.f);
        }
    }
    __syncthreads();

    // ---- load W2 hi/lo images (overwrite Wc region) ----
    float* sW2h = sWh;
    float* sW2l = sWh + DOUT * ASTR;
    for (int i = tid; i < DOUT * 32; i += 512) {
        int r = i >> 5, c4 = (i & 31) << 2;
        *reinterpret_cast<float4*>(&sW2h[r * ASTR + c4]) =
            *reinterpret_cast<const float4*>(&g_W2T_h[r * D + c4]);
        *reinterpret_cast<float4*>(&sW2l[r * ASTR + c4]) =
            *reinterpret_cast<const float4*>(&g_W2T_l[r * D + c4]);
    }
    __syncthreads();

    // ---- layer 2: warp tile 32 rows x 16 cols ----
    int cw2 = (w & 3) * 16;
    float acc2[2][2][4];
#pragma unroll
    for (int mt = 0; mt < 2; mt++)
#pragma unroll
        for (int nt = 0; nt < 2; nt++)
#pragma unroll
            for (int j = 0; j < 4; j++) acc2[mt][nt][j] = 0.f;

#pragma unroll 4
    for (int ks = 0; ks < 16; ks++) {
        int k0 = ks * 8;
        uint32_t ah[2][4], al[2][4];
#pragma unroll
        for (int mt = 0; mt < 2; mt++) {
            int rb = rw0 + mt * 16;
            float f0 = sA[(rb + g) * ASTR + k0 + qi];
            float f1 = sA[(rb + g + 8) * ASTR + k0 + qi];
            float f2 = sA[(rb + g) * ASTR + k0 + qi + 4];
            float f3 = sA[(rb + g + 8) * ASTR + k0 + qi + 4];
            split_tf32(f0, ah[mt][0], al[mt][0]);
            split_tf32(f1, ah[mt][1], al[mt][1]);
            split_tf32(f2, ah[mt][2], al[mt][2]);
            split_tf32(f3, ah[mt][3], al[mt][3]);
        }
#pragma unroll
        for (int nt = 0; nt < 2; nt++) {
            int nb = cw2 + nt * 8;
            uint32_t bh0 = __float_as_uint(sW2h[(nb + g) * ASTR + k0 + qi]);
            uint32_t bh1 = __float_as_uint(sW2h[(nb + g) * ASTR + k0 + qi + 4]);
            uint32_t bl0 = __float_as_uint(sW2l[(nb + g) * ASTR + k0 + qi]);
            uint32_t bl1 = __float_as_uint(sW2l[(nb + g) * ASTR + k0 + qi + 4]);
#pragma unroll
            for (int mt = 0; mt < 2; mt++) {
                mma_tf32(acc2[mt][nt], ah[mt], bh0, bh1);
                mma_tf32(acc2[mt][nt], ah[mt], bl0, bl1);
                mma_tf32(acc2[mt][nt], al[mt], bh0, bh1);
            }
        }
    }
    __syncthreads();

    // ---- epilogue 2: stage h2 in smem (stride 66), coalesced store ----
    float* h2s = sA;
#pragma unroll
    for (int mt = 0; mt < 2; mt++) {
        int rb = rw0 + mt * 16;
#pragma unroll
        for (int nt = 0; nt < 2; nt++) {
            int c0 = cw2 + nt * 8 + qi * 2;
            h2s[(rb + g) * 66 + c0]         = acc2[mt][nt][0];
            h2s[(rb + g) * 66 + c0 + 1]     = acc2[mt][nt][1];
            h2s[(rb + g + 8) * 66 + c0]     = acc2[mt][nt][2];
            h2s[(rb + g + 8) * 66 + c0 + 1] = acc2[mt][nt][3];
        }
    }
    __syncthreads();
    for (int i = tid; i < 128 * 32; i += 512) {
        int r = i >> 5, c2 = (i & 31) << 1;
        int row = row0 + r;
        if (row < N_NODES) {
            float2 v = *reinterpret_cast<const float2*>(&h2s[r * 66 + c2]);
            *reinterpret_cast<float2*>(&g_h2[(size_t)row * DOUT + c2]) = v;
        }
    }
}

// ---------------------------------------------------------------------------
// Gather layer 2 + bias + L2 normalize, fused (64 dims) — 4x unrolled
// ---------------------------------------------------------------------------
__global__ void gather2_kernel(const float* __restrict__ b2,
                               float* __restrict__ out) {
    int node = (blockIdx.x * blockDim.x + threadIdx.x) >> 5;
    int lane = threadIdx.x & 31;
    if (node >= N_NODES) return;
    int beg = g_rowptr[node];
    int end = g_rowptr[node + 1];

    float2 acc = *reinterpret_cast<const float2*>(g_h2 + (size_t)node * DOUT + lane * 2);

    for (int base = beg; base < end; base += 32) {
        int idx = 0;
        if (base + lane < end) idx = __ldg(&g_csr_src[base + lane]);
        int m = end - base; if (m > 32) m = 32;
        int j = 0;
        for (; j + 4 <= m; j += 4) {
            int s0 = __shfl_sync(0xffffffffu, idx, j);
            int s1 = __shfl_sync(0xffffffffu, idx, j + 1);
            int s2 = __shfl_sync(0xffffffffu, idx, j + 2);
            int s3 = __shfl_sync(0xffffffffu, idx, j + 3);
            float2 v0 = *reinterpret_cast<const float2*>(g_h2 + (size_t)s0 * DOUT + lane * 2);
            float2 v1 = *reinterpret_cast<const float2*>(g_h2 + (size_t)s1 * DOUT + lane * 2);
            float2 v2 = *reinterpret_cast<const float2*>(g_h2 + (size_t)s2 * DOUT + lane * 2);
            float2 v3 = *reinterpret_cast<const float2*>(g_h2 + (size_t)s3 * DOUT + lane * 2);
            acc.x += (v0.x + v1.x) + (v2.x + v3.x);
            acc.y += (v0.y + v1.y) + (v2.y + v3.y);
        }
        for (; j < m; j++) {
            int s = __shfl_sync(0xffffffffu, idx, j);
            float2 v = *reinterpret_cast<const float2*>(g_h2 + (size_t)s * DOUT + lane * 2);
            acc.x += v.x; acc.y += v.y;
        }
    }
    float inv = 1.0f / (float)(end - beg + 1);
    float2 b = *reinterpret_cast<const float2*>(b2 + lane * 2);
    float a0 = acc.x * inv + b.x;
    float a1 = acc.y * inv + b.y;
    float ss = a0 * a0 + a1 * a1;
#pragma unroll
    for (int o = 16; o; o >>= 1) ss += __shfl_xor_sync(0xffffffffu, ss, o);
    float s = 1.0f / fmaxf(sqrtf(ss), 1e-12f);
    float2 o2 = make_float2(a0 * s, a1 * s);
    *reinterpret_cast<float2*>(&out[(size_t)node * DOUT + lane * 2]) = o2;
}

// ---------------------------------------------------------------------------
extern "C" void kernel_launch(void* const* d_in, const int* in_sizes, int n_in,
                              void* d_out, int out_size) {
    const float* x     = (const float*)d_in[0];
    const int*   ei    = (const int*)d_in[1];
    const float* W_pre = (const float*)d_in[2];
    const float* b_pre = (const float*)d_in[3];
    const float* W1    = (const float*)d_in[4];
    const float* b1    = (const float*)d_in[5];
    const float* W2    = (const float*)d_in[6];
    const float* b2    = (const float*)d_in[7];
    float* out = (float*)d_out;

    const int* src = ei;
    const int* dst = ei + E_EDGES;

    static void* rowcnt_ptr = nullptr;
    static bool attr_set = false;
    if (!attr_set) {
        cudaFuncSetAttribute(fusedgemm_kernel,
                             cudaFuncAttributeMaxDynamicSharedMemorySize, FG_SMEM);
        cudaGetSymbolAddress(&rowcnt_ptr, g_rowcnt);
        attr_set = true;
    }

    prep_kernel<<<D + 1 + DOUT, D>>>(W_pre, b_pre, W1, b1, W2);
    cudaMemsetAsync(rowcnt_ptr, 0, N_NODES * sizeof(int));
    hist_kernel<<<(E_EDGES + 255) / 256, 256>>>(dst);
    scan1_kernel<<<SCAN_GRID, 256>>>();
    scan3_kernel<<<SCAN_GRID, 256>>>();
    fill_kernel<<<(E_EDGES + 255) / 256, 256>>>(src, dst);
    gather1_kernel<<<(N_NODES * 32 + 255) / 256, 256>>>(x);
    fusedgemm_kernel<<<(N_NODES + 127) / 128, 512, FG_SMEM>>>();
    gather2_kernel<<<(N_NODES * 32 + 255) / 256, 256>>>(b2, out);
}